// round 1
// baseline (speedup 1.0000x reference)
#include <cuda_runtime.h>
#include <cuda_fp16.h>
#include <stdint.h>

#define N_ROWS   262144
#define TILE_M   128
#define NTHREADS 256
#define SMEM_BYTES 179200

// fp16 weights: W2 [256][128] @0, W3 [128][256] @32768, W4 [512][128] @65536
__device__ __half g_Wh[131072];

__global__ void cvt_weights_kernel(const float* __restrict__ W2,
                                   const float* __restrict__ W3,
                                   const float* __restrict__ W4) {
    int i = blockIdx.x * blockDim.x + threadIdx.x;   // 65536 threads
    if (i < 32768) {
        g_Wh[i]         = __float2half_rn(W2[i]);
        g_Wh[32768 + i] = __float2half_rn(W3[i]);
    }
    g_Wh[65536 + i] = __float2half_rn(W4[i]);
}

__device__ __forceinline__ uint32_t smem_u32(const void* p) {
    return (uint32_t)__cvta_generic_to_shared(p);
}

__device__ __forceinline__ void ldmatrix_x4(uint32_t r[4], uint32_t addr) {
    asm volatile("ldmatrix.sync.aligned.m8n8.x4.shared.b16 {%0,%1,%2,%3}, [%4];\n"
                 : "=r"(r[0]), "=r"(r[1]), "=r"(r[2]), "=r"(r[3]) : "r"(addr));
}

__device__ __forceinline__ void mma16816(float c[4], const uint32_t a[4], uint32_t b0, uint32_t b1) {
    asm volatile("mma.sync.aligned.m16n8k16.row.col.f32.f16.f16.f32 "
                 "{%0,%1,%2,%3},{%4,%5,%6,%7},{%8,%9},{%0,%1,%2,%3};\n"
                 : "+f"(c[0]), "+f"(c[1]), "+f"(c[2]), "+f"(c[3])
                 : "r"(a[0]), "r"(a[1]), "r"(a[2]), "r"(a[3]), "r"(b0), "r"(b1));
}

// tanh-GELU in sigmoid form: gelu(x) = x * sigmoid(1.5957691x + 0.0713548x^3)
__device__ __forceinline__ float fast_gelu(float x) {
    float x3 = x * x * x;
    float z  = fmaf(0.0713548162726f, x3, 1.5957691216057308f * x);
    float e  = __expf(-z);
    return __fdividef(x, 1.0f + e);
}

// copy fp16 weight block [nrows][kh] (dense) into smem with row stride ld (halves)
__device__ __forceinline__ void copy_w(const __half* __restrict__ src, int nrows, int kh,
                                       __half* dst, int ld, int tid) {
    int nv  = kh >> 3;            // uint4 per row
    int tot = nrows * nv;
    for (int i = tid; i < tot; i += NTHREADS) {
        int r = i / nv, c = (i - r * nv) << 3;
        *(uint4*)(dst + r * ld + c) = *(const uint4*)(src + r * kh + c);
    }
}

// GEMM [128 x K] @ W[NOUT x K]^T -> gelu -> half into sOut [128 x NOUT]
template <int K, int NOUT, int LDI, int LDW, int LDO>
__device__ __forceinline__ void gemm_gelu(const __half* sIn, const __half* sWt,
                                          const float* sBias, __half* sOut,
                                          int lane, int r0) {
    int mi = lane >> 3, ri = lane & 7;
    int g  = lane >> 2, tg = lane & 3;
    uint32_t aBase = smem_u32(sIn) + (uint32_t)(((r0 + ri + ((mi & 1) << 3)) * LDI + ((mi >> 1) << 3)) * 2);
    uint32_t wBase = smem_u32(sWt) + (uint32_t)(((ri + ((mi & 1) << 3)) * LDW + ((mi >> 1) << 3)) * 2);

#pragma unroll
    for (int nc = 0; nc < NOUT; nc += 64) {
        float acc[4][2][4];
#pragma unroll
        for (int p = 0; p < 4; ++p)
#pragma unroll
            for (int h = 0; h < 2; ++h)
#pragma unroll
                for (int q = 0; q < 4; ++q) acc[p][h][q] = 0.0f;

#pragma unroll
        for (int k = 0; k < K; k += 16) {
            uint32_t a[4];
            ldmatrix_x4(a, aBase + (uint32_t)(k * 2));
#pragma unroll
            for (int p = 0; p < 4; ++p) {
                uint32_t bb[4];
                ldmatrix_x4(bb, wBase + (uint32_t)((((nc + 16 * p) * LDW) + k) * 2));
                mma16816(acc[p][0], a, bb[0], bb[2]);
                mma16816(acc[p][1], a, bb[1], bb[3]);
            }
        }

#pragma unroll
        for (int p = 0; p < 4; ++p)
#pragma unroll
            for (int h = 0; h < 2; ++h) {
                int col = nc + 16 * p + 8 * h + tg * 2;
                float bx = sBias[col], by = sBias[col + 1];
                int row = r0 + g;
                __half2 v0, v1;
                v0.x = __float2half_rn(fast_gelu(acc[p][h][0] + bx));
                v0.y = __float2half_rn(fast_gelu(acc[p][h][1] + by));
                *(__half2*)&sOut[row * LDO + col] = v0;
                v1.x = __float2half_rn(fast_gelu(acc[p][h][2] + bx));
                v1.y = __float2half_rn(fast_gelu(acc[p][h][3] + by));
                *(__half2*)&sOut[(row + 8) * LDO + col] = v1;
            }
    }
}

// Final GEMM chunk (NOUT=256 cols starting at base_n) with emb add + pad override, direct STG
template <int K, int LDI, int LDW>
__device__ __forceinline__ void gemm_out(const __half* sIn, const __half* sWt,
                                         const float* __restrict__ emb,
                                         const int* sTok, const int* sPad,
                                         float* __restrict__ out,
                                         int base_n, int R0, int lane, int r0) {
    int mi = lane >> 3, ri = lane & 7;
    int g  = lane >> 2, tg = lane & 3;
    uint32_t aBase = smem_u32(sIn) + (uint32_t)(((r0 + ri + ((mi & 1) << 3)) * LDI + ((mi >> 1) << 3)) * 2);
    uint32_t wBase = smem_u32(sWt) + (uint32_t)(((ri + ((mi & 1) << 3)) * LDW + ((mi >> 1) << 3)) * 2);

#pragma unroll
    for (int nc = 0; nc < 256; nc += 64) {
        float acc[4][2][4];
#pragma unroll
        for (int p = 0; p < 4; ++p)
#pragma unroll
            for (int h = 0; h < 2; ++h)
#pragma unroll
                for (int q = 0; q < 4; ++q) acc[p][h][q] = 0.0f;

#pragma unroll
        for (int k = 0; k < K; k += 16) {
            uint32_t a[4];
            ldmatrix_x4(a, aBase + (uint32_t)(k * 2));
#pragma unroll
            for (int p = 0; p < 4; ++p) {
                uint32_t bb[4];
                ldmatrix_x4(bb, wBase + (uint32_t)((((nc + 16 * p) * LDW) + k) * 2));
                mma16816(acc[p][0], a, bb[0], bb[2]);
                mma16816(acc[p][1], a, bb[1], bb[3]);
            }
        }

#pragma unroll
        for (int p = 0; p < 4; ++p)
#pragma unroll
            for (int h = 0; h < 2; ++h) {
                int coll = base_n + nc + 16 * p + 8 * h + tg * 2;
#pragma unroll
                for (int rr = 0; rr < 2; ++rr) {
                    int row = r0 + g + rr * 8;
                    float a0 = acc[p][h][rr * 2 + 0];
                    float a1 = acc[p][h][rr * 2 + 1];
                    int pad = sPad[row];
                    int tok = pad ? 0 : sTok[row];
                    float2 ev = *(const float2*)(emb + tok * 512 + coll);
                    float2 o;
                    o.x = pad ? ev.x : (a0 + ev.x);
                    o.y = pad ? ev.y : (a1 + ev.y);
                    *(float2*)(out + (size_t)(R0 + row) * 512 + coll) = o;
                }
            }
    }
}

__global__ __launch_bounds__(NTHREADS, 1)
void embedder_kernel(const float* __restrict__ joint_info,
                     const int* __restrict__ joint_token,
                     const float* __restrict__ emb,
                     const float* __restrict__ W1, const float* __restrict__ b1,
                     const float* __restrict__ b2, const float* __restrict__ b3,
                     float* __restrict__ out) {
    extern __shared__ char smem[];
    __half* sW   = (__half*)(smem);              // 69632 B (max 256x136 halves)
    __half* sH1  = (__half*)(smem + 69632);      // 34816 B (128x136) h1 / h3
    __half* sH2  = (__half*)(smem + 104448);     // 67584 B (128x264) h2
    float4* sX   = (float4*)(smem + 172032);     // 2048 B
    float*  sW1  = (float*)(smem + 174080);      // 2048 B
    float*  sB1  = (float*)(smem + 176128);      // 512 B
    float*  sB2  = (float*)(smem + 176640);      // 1024 B
    float*  sB3  = (float*)(smem + 177664);      // 512 B
    int*    sTok = (int*)(smem + 178176);        // 512 B
    int*    sPad = (int*)(smem + 178688);        // 512 B

    int tid  = threadIdx.x;
    int lane = tid & 31, warp = tid >> 5;
    int R0   = blockIdx.x * TILE_M;

    if (tid < 128) {
        float4 x = ((const float4*)joint_info)[R0 + tid];
        sX[tid]   = x;
        sTok[tid] = joint_token[R0 + tid];
        sPad[tid] = (x.x == 0.0f && x.y == 0.0f && x.z == 0.0f && x.w == 0.0f) ? 1 : 0;
        sB1[tid]  = b1[tid];
        sB3[tid]  = b3[tid];
    }
    sB2[tid] = b2[tid];
    ((float2*)sW1)[tid] = ((const float2*)W1)[tid];   // 512 floats of W1
    copy_w(g_Wh, 256, 128, sW, 136, tid);             // W2
    __syncthreads();

    // ---- layer 1 (K=4) scalar fp32, exact weights ----
    {
        int c = tid & 127;
        int rbase = (tid >> 7) * 64;
        float w0 = sW1[c * 4 + 0], w1 = sW1[c * 4 + 1];
        float w2 = sW1[c * 4 + 2], w3 = sW1[c * 4 + 3];
        float bb = sB1[c];
        for (int r = rbase; r < rbase + 64; ++r) {
            float4 x = sX[r];
            float y  = fmaf(x.x, w0, fmaf(x.y, w1, fmaf(x.z, w2, fmaf(x.w, w3, bb))));
            sH1[r * 136 + c] = __float2half_rn(fast_gelu(y));
        }
    }
    __syncthreads();

    // ---- layer 2: h1[128x128] @ W2[256x128]^T -> h2[128x256] ----
    gemm_gelu<128, 256, 136, 136, 264>(sH1, sW, sB2, sH2, lane, warp * 16);
    __syncthreads();
    copy_w(g_Wh + 32768, 128, 256, sW, 264, tid);     // W3
    __syncthreads();

    // ---- layer 3: h2[128x256] @ W3[128x256]^T -> h3[128x128] (overwrites sH1) ----
    gemm_gelu<256, 128, 264, 264, 136>(sH2, sW, sB3, sH1, lane, warp * 16);
    __syncthreads();
    copy_w(g_Wh + 65536, 256, 128, sW, 136, tid);     // W4 rows 0..255
    __syncthreads();

    // ---- layer 4a: cols [0,256) with emb/pad epilogue ----
    gemm_out<128, 136, 136>(sH1, sW, emb, sTok, sPad, out, 0, R0, lane, warp * 16);
    __syncthreads();
    copy_w(g_Wh + 65536 + 32768, 256, 128, sW, 136, tid);  // W4 rows 256..511
    __syncthreads();

    // ---- layer 4b: cols [256,512) ----
    gemm_out<128, 136, 136>(sH1, sW, emb, sTok, sPad, out, 256, R0, lane, warp * 16);
}

extern "C" void kernel_launch(void* const* d_in, const int* in_sizes, int n_in,
                              void* d_out, int out_size) {
    const float* joint_info  = (const float*)d_in[0];
    const int*   joint_token = (const int*)d_in[1];
    const float* emb         = (const float*)d_in[2];
    const float* W1          = (const float*)d_in[3];
    const float* b1          = (const float*)d_in[4];
    const float* W2          = (const float*)d_in[5];
    const float* b2          = (const float*)d_in[6];
    const float* W3          = (const float*)d_in[7];
    const float* b3          = (const float*)d_in[8];
    const float* W4          = (const float*)d_in[9];

    cvt_weights_kernel<<<256, 256>>>(W2, W3, W4);

    cudaFuncSetAttribute(embedder_kernel,
                         cudaFuncAttributeMaxDynamicSharedMemorySize, SMEM_BYTES);
    embedder_kernel<<<N_ROWS / TILE_M, NTHREADS, SMEM_BYTES>>>(
        joint_info, joint_token, emb, W1, b1, b2, b3, (float*)d_out);
}

// round 2
// speedup vs baseline: 1.5726x; 1.5726x over previous
#include <cuda_runtime.h>
#include <cuda_fp16.h>
#include <stdint.h>

#define N_ROWS   262144
#define TILE_M   128
#define NTHREADS 256
#define SMEM_BYTES 146432

// fp16 weights: W2 [256][128] @0, W3 [128][256] @32768, W4 [512][128] @65536
__device__ __half g_Wh[131072];

__global__ void cvt_weights_kernel(const float* __restrict__ W2,
                                   const float* __restrict__ W3,
                                   const float* __restrict__ W4) {
    int i = blockIdx.x * blockDim.x + threadIdx.x;   // 65536 threads
    if (i < 32768) {
        g_Wh[i]         = __float2half_rn(W2[i]);
        g_Wh[32768 + i] = __float2half_rn(W3[i]);
    }
    g_Wh[65536 + i] = __float2half_rn(W4[i]);
}

__device__ __forceinline__ uint32_t smem_u32(const void* p) {
    return (uint32_t)__cvta_generic_to_shared(p);
}

__device__ __forceinline__ void ldmatrix_x4(uint32_t r[4], uint32_t addr) {
    asm volatile("ldmatrix.sync.aligned.m8n8.x4.shared.b16 {%0,%1,%2,%3}, [%4];\n"
                 : "=r"(r[0]), "=r"(r[1]), "=r"(r[2]), "=r"(r[3]) : "r"(addr));
}

__device__ __forceinline__ void mma16816(float c[4], const uint32_t a[4], uint32_t b0, uint32_t b1) {
    asm volatile("mma.sync.aligned.m16n8k16.row.col.f32.f16.f16.f32 "
                 "{%0,%1,%2,%3},{%4,%5,%6,%7},{%8,%9},{%0,%1,%2,%3};\n"
                 : "+f"(c[0]), "+f"(c[1]), "+f"(c[2]), "+f"(c[3])
                 : "r"(a[0]), "r"(a[1]), "r"(a[2]), "r"(a[3]), "r"(b0), "r"(b1));
}

__device__ __forceinline__ void cp_async16(uint32_t dst_smem, const void* src) {
    asm volatile("cp.async.cg.shared.global [%0], [%1], 16;\n" :: "r"(dst_smem), "l"(src));
}
__device__ __forceinline__ void cp_commit() { asm volatile("cp.async.commit_group;\n"); }
template <int n>
__device__ __forceinline__ void cp_wait() { asm volatile("cp.async.wait_group %0;\n" :: "n"(n)); }

// tanh-GELU in sigmoid form: gelu(x) = x * sigmoid(1.5957691x + 0.0713548x^3)
__device__ __forceinline__ float fast_gelu(float x) {
    float x3 = x * x * x;
    float z  = fmaf(0.0713548162726f, x3, 1.5957691216057308f * x);
    float e  = __expf(-z);
    return __fdividef(x, 1.0f + e);
}

__device__ __forceinline__ uint32_t pack_h2(float a, float b) {
    __half2 h = __floats2half2_rn(a, b);
    return *(uint32_t*)&h;
}

// async copy fp16 weight block [nrows][kh] (dense global) into smem with row stride ld (halves)
__device__ __forceinline__ void copy_w_async(const __half* __restrict__ src, int nrows, int kh,
                                             uint32_t dst_u32, int ld, int tid) {
    int nv  = kh >> 3;            // 16B chunks per row
    int tot = nrows * nv;
    for (int i = tid; i < tot; i += NTHREADS) {
        int r = i / nv, c = (i - r * nv) << 3;
        cp_async16(dst_u32 + (uint32_t)((r * ld + c) * 2), src + r * kh + c);
    }
}

__global__ __launch_bounds__(NTHREADS, 1)
void embedder_kernel(const float* __restrict__ joint_info,
                     const int* __restrict__ joint_token,
                     const float* __restrict__ emb,
                     const float* __restrict__ W1, const float* __restrict__ b1,
                     const float* __restrict__ b2, const float* __restrict__ b3,
                     float* __restrict__ out) {
    extern __shared__ char smem[];
    // bufA @0 (69632B, up to 256x136 halves), bufB @69632 (69632B)
    float4* sX   = (float4*)(smem + 139264);     // 2048 B
    float*  sW1  = (float*)(smem + 141312);      // 2048 B
    float*  sB1  = (float*)(smem + 143360);      // 512 B
    float*  sB2  = (float*)(smem + 143872);      // 1024 B
    float*  sB3  = (float*)(smem + 144896);      // 512 B
    int*    sTok = (int*)(smem + 145408);        // 512 B
    int*    sPad = (int*)(smem + 145920);        // 512 B

    uint32_t bufA = smem_u32(smem);
    uint32_t bufB = bufA + 69632;

    int tid  = threadIdx.x;
    int lane = tid & 31, warp = tid >> 5;
    int R0   = blockIdx.x * TILE_M;

    // ---- plain loads of small data ----
    if (tid < 128) {
        float4 x = ((const float4*)joint_info)[R0 + tid];
        sX[tid]   = x;
        sTok[tid] = joint_token[R0 + tid];
        sPad[tid] = (x.x == 0.0f && x.y == 0.0f && x.z == 0.0f && x.w == 0.0f) ? 1 : 0;
        sB1[tid]  = b1[tid];
        sB3[tid]  = b3[tid];
    }
    sB2[tid] = b2[tid];
    ((float2*)sW1)[tid] = ((const float2*)W1)[tid];   // 512 floats of W1

    // ---- prefetch W2 -> bufA, W3 -> bufB ----
    copy_w_async(g_Wh, 256, 128, bufA, 136, tid);        // group: W2
    cp_commit();
    copy_w_async(g_Wh + 32768, 128, 256, bufB, 264, tid); // group: W3
    cp_commit();
    __syncthreads();   // sX/sW1/biases visible

    // per-lane fragment coords
    int g = lane >> 2, t = lane & 3;            // C/A fragment coords
    int mi = lane >> 3, ri = lane & 7;          // ldmatrix coords
    int wrow = ri + ((mi & 1) << 3);
    int wcol = (mi >> 1) << 3;
    int r0 = warp * 16;

    // ---- layer 1 (K=4) scalar fp32 -> h1 A-fragments (16 rows x 128 cols per warp) ----
    uint32_t h1A[8][4];
    {
        float4 xa = sX[r0 + g];
        float4 xb = sX[r0 + g + 8];
#pragma unroll
        for (int kt = 0; kt < 8; ++kt)
#pragma unroll
            for (int j = 0; j < 2; ++j) {
                int c0 = kt * 16 + j * 8 + t * 2;
                float4 w0 = *(const float4*)&sW1[c0 * 4];
                float4 w1 = *(const float4*)&sW1[(c0 + 1) * 4];
                float bb0 = sB1[c0], bb1 = sB1[c0 + 1];
                float ya0 = fmaf(xa.x, w0.x, fmaf(xa.y, w0.y, fmaf(xa.z, w0.z, fmaf(xa.w, w0.w, bb0))));
                float ya1 = fmaf(xa.x, w1.x, fmaf(xa.y, w1.y, fmaf(xa.z, w1.z, fmaf(xa.w, w1.w, bb1))));
                float yb0 = fmaf(xb.x, w0.x, fmaf(xb.y, w0.y, fmaf(xb.z, w0.z, fmaf(xb.w, w0.w, bb0))));
                float yb1 = fmaf(xb.x, w1.x, fmaf(xb.y, w1.y, fmaf(xb.z, w1.z, fmaf(xb.w, w1.w, bb1))));
                h1A[kt][2 * j + 0] = pack_h2(fast_gelu(ya0), fast_gelu(ya1));
                h1A[kt][2 * j + 1] = pack_h2(fast_gelu(yb0), fast_gelu(yb1));
            }
    }

    cp_wait<1>();        // W2 ready
    __syncthreads();

    // ---- layer 2: h1[16x128] @ W2[256x128]^T -> h2 fragments (K for layer3) ----
    uint32_t h2A[16][4];
    {
        uint32_t wb = bufA + (uint32_t)((wrow * 136 + wcol) * 2);
#pragma unroll
        for (int ng = 0; ng < 16; ++ng) {
            int n0 = ng * 16;
            float c[8] = {0, 0, 0, 0, 0, 0, 0, 0};
#pragma unroll
            for (int kt = 0; kt < 8; ++kt) {
                uint32_t bb[4];
                ldmatrix_x4(bb, wb + (uint32_t)(n0 * 272 + kt * 32));
                mma16816(c + 0, h1A[kt], bb[0], bb[2]);
                mma16816(c + 4, h1A[kt], bb[1], bb[3]);
            }
            float b0 = sB2[n0 + 2 * t], b1v = sB2[n0 + 2 * t + 1];
            float b2v = sB2[n0 + 8 + 2 * t], b3v = sB2[n0 + 9 + 2 * t];
            h2A[ng][0] = pack_h2(fast_gelu(c[0] + b0), fast_gelu(c[1] + b1v));
            h2A[ng][1] = pack_h2(fast_gelu(c[2] + b0), fast_gelu(c[3] + b1v));
            h2A[ng][2] = pack_h2(fast_gelu(c[4] + b2v), fast_gelu(c[5] + b3v));
            h2A[ng][3] = pack_h2(fast_gelu(c[6] + b2v), fast_gelu(c[7] + b3v));
        }
    }

    __syncthreads();     // all warps done with bufA
    copy_w_async(g_Wh + 65536, 256, 128, bufA, 136, tid);  // group: W4a
    cp_commit();
    cp_wait<1>();        // W3 ready (W4a still in flight)
    __syncthreads();

    // ---- layer 3: h2[16x256] @ W3[128x256]^T -> h3 fragments ----
    uint32_t h3A[8][4];
    {
        uint32_t wb = bufB + (uint32_t)((wrow * 264 + wcol) * 2);
#pragma unroll
        for (int ng = 0; ng < 8; ++ng) {
            int n0 = ng * 16;
            float c[8] = {0, 0, 0, 0, 0, 0, 0, 0};
#pragma unroll
            for (int kt = 0; kt < 16; ++kt) {
                uint32_t bb[4];
                ldmatrix_x4(bb, wb + (uint32_t)(n0 * 528 + kt * 32));
                mma16816(c + 0, h2A[kt], bb[0], bb[2]);
                mma16816(c + 4, h2A[kt], bb[1], bb[3]);
            }
            float b0 = sB3[n0 + 2 * t], b1v = sB3[n0 + 2 * t + 1];
            float b2v = sB3[n0 + 8 + 2 * t], b3v = sB3[n0 + 9 + 2 * t];
            h3A[ng][0] = pack_h2(fast_gelu(c[0] + b0), fast_gelu(c[1] + b1v));
            h3A[ng][1] = pack_h2(fast_gelu(c[2] + b0), fast_gelu(c[3] + b1v));
            h3A[ng][2] = pack_h2(fast_gelu(c[4] + b2v), fast_gelu(c[5] + b3v));
            h3A[ng][3] = pack_h2(fast_gelu(c[6] + b2v), fast_gelu(c[7] + b3v));
        }
    }

    __syncthreads();     // all warps done with bufB
    copy_w_async(g_Wh + 65536 + 32768, 256, 128, bufB, 136, tid);  // group: W4b
    cp_commit();
    cp_wait<1>();        // W4a ready (W4b still in flight)
    __syncthreads();

    // ---- layer 4 epilogue setup (per-thread constants) ----
    int pa = sPad[r0 + g], pb = sPad[r0 + g + 8];
    int ta = pa ? 0 : sTok[r0 + g];
    int tb = pb ? 0 : sTok[r0 + g + 8];
    const float* ea = emb + ta * 512;
    const float* eb = emb + tb * 512;
    float* outa = out + (size_t)(R0 + r0 + g) * 512;
    float* outb = out + (size_t)(R0 + r0 + g + 8) * 512;

#pragma unroll
    for (int half = 0; half < 2; ++half) {
        uint32_t wb = (half == 0 ? bufA : bufB) + (uint32_t)((wrow * 136 + wcol) * 2);
        int base_n = half * 256;
#pragma unroll
        for (int ng = 0; ng < 16; ++ng) {
            int n0 = ng * 16;
            float c[8] = {0, 0, 0, 0, 0, 0, 0, 0};
#pragma unroll
            for (int kt = 0; kt < 8; ++kt) {
                uint32_t bb[4];
                ldmatrix_x4(bb, wb + (uint32_t)(n0 * 272 + kt * 32));
                mma16816(c + 0, h3A[kt], bb[0], bb[2]);
                mma16816(c + 4, h3A[kt], bb[1], bb[3]);
            }
            int c0 = base_n + n0 + 2 * t;
            int c1 = base_n + n0 + 8 + 2 * t;
            float2 e, o;
            e = *(const float2*)(ea + c0);
            o.x = pa ? e.x : (c[0] + e.x);  o.y = pa ? e.y : (c[1] + e.y);
            *(float2*)(outa + c0) = o;
            e = *(const float2*)(eb + c0);
            o.x = pb ? e.x : (c[2] + e.x);  o.y = pb ? e.y : (c[3] + e.y);
            *(float2*)(outb + c0) = o;
            e = *(const float2*)(ea + c1);
            o.x = pa ? e.x : (c[4] + e.x);  o.y = pa ? e.y : (c[5] + e.y);
            *(float2*)(outa + c1) = o;
            e = *(const float2*)(eb + c1);
            o.x = pb ? e.x : (c[6] + e.x);  o.y = pb ? e.y : (c[7] + e.y);
            *(float2*)(outb + c1) = o;
        }
        if (half == 0) {
            cp_wait<0>();    // W4b ready
            __syncthreads();
        }
    }
}

extern "C" void kernel_launch(void* const* d_in, const int* in_sizes, int n_in,
                              void* d_out, int out_size) {
    const float* joint_info  = (const float*)d_in[0];
    const int*   joint_token = (const int*)d_in[1];
    const float* emb         = (const float*)d_in[2];
    const float* W1          = (const float*)d_in[3];
    const float* b1          = (const float*)d_in[4];
    const float* W2          = (const float*)d_in[5];
    const float* b2          = (const float*)d_in[6];
    const float* W3          = (const float*)d_in[7];
    const float* b3          = (const float*)d_in[8];
    const float* W4          = (const float*)d_in[9];

    cvt_weights_kernel<<<256, 256>>>(W2, W3, W4);

    cudaFuncSetAttribute(embedder_kernel,
                         cudaFuncAttributeMaxDynamicSharedMemorySize, SMEM_BYTES);
    embedder_kernel<<<N_ROWS / TILE_M, NTHREADS, SMEM_BYTES>>>(
        joint_info, joint_token, emb, W1, b1, b2, b3, (float*)d_out);
}